// round 12
// baseline (speedup 1.0000x reference)
#include <cuda_runtime.h>
#include <cstdint>

#define FULL_MASK 0xFFFFFFFFu
#define NQ 8
#define DEPTH 3
#define FDIM 512
#define NCLS 10
#define BTHREADS 128
#define MAXB 8192

typedef unsigned long long u64;

// ---- device-global scratch (allocation-free) ----
__device__ float2 g_cs[MAXB * NQ];      // (cos, sin) of half-angle per (b, q)
__device__ float4 g_gates[DEPTH * NQ][2];

// ---- packed f32x2 helpers ----
__device__ __forceinline__ u64 pk2(float lo, float hi) {
    u64 r; asm("mov.b64 %0,{%1,%2};" : "=l"(r) : "f"(lo), "f"(hi)); return r;
}
__device__ __forceinline__ void up2(u64 v, float& lo, float& hi) {
    asm("mov.b64 {%0,%1},%2;" : "=f"(lo), "=f"(hi) : "l"(v));
}
__device__ __forceinline__ u64 fma2_(u64 a, u64 b, u64 c) {
    u64 d; asm("fma.rn.f32x2 %0,%1,%2,%3;" : "=l"(d) : "l"(a), "l"(b), "l"(c)); return d;
}
__device__ __forceinline__ u64 mul2_(u64 a, u64 b) {
    u64 d; asm("mul.rn.f32x2 %0,%1,%2;" : "=l"(d) : "l"(a), "l"(b)); return d;
}
__device__ __forceinline__ u64 add2_(u64 a, u64 b) {
    u64 d; asm("add.rn.f32x2 %0,%1,%2;" : "=l"(d) : "l"(a), "l"(b)); return d;
}
__device__ __forceinline__ u64 neg2_(u64 a) { return a ^ 0x8000000080000000ULL; }
__device__ __forceinline__ u64 bc2(float c) { return pk2(c, c); }
__device__ __forceinline__ u64 swp2(u64 v) { float lo, hi; up2(v, lo, hi); return pk2(hi, lo); }

// ============================================================
// Kernel 1: projection + tanh + half-angle sincos -> g_cs ; gates -> g_gates
// (unchanged - proven)
// ============================================================
__global__ void __launch_bounds__(BTHREADS, 8) proj_kernel(
    const float* __restrict__ x,
    const float* __restrict__ proj_w,
    const float* __restrict__ qnn_w,
    int B)
{
    const int tid  = threadIdx.x;
    const int lane = tid & 31;
    const int warp = tid >> 5;

    if (blockIdx.x == 0 && tid < DEPTH * NQ) {
        float w0 = qnn_w[tid * 3 + 0];
        float w1 = qnn_w[tid * 3 + 1];
        float w2 = qnn_w[tid * 3 + 2];
        float c0, s0, c1, s1, c2, s2;
        sincosf(0.5f * w0, &s0, &c0);
        sincosf(0.5f * w1, &s1, &c1);
        sincosf(0.5f * w2, &s2, &c2);
        float2 A00 = { c1 * c0,  s1 * s0};
        float2 A01 = {-s1 * c0, -c1 * s0};
        float2 A10 = { s1 * c0, -c1 * s0};
        float2 A11 = { c1 * c0, -s1 * s0};
        float2 q00 = make_float2(c2 * A00.x + s2 * A10.y, c2 * A00.y - s2 * A10.x);
        float2 q01 = make_float2(c2 * A01.x + s2 * A11.y, c2 * A01.y - s2 * A11.x);
        float2 q10 = make_float2(c2 * A10.x + s2 * A00.y, c2 * A10.y - s2 * A00.x);
        float2 q11 = make_float2(c2 * A11.x + s2 * A01.y, c2 * A11.y - s2 * A01.x);
        g_gates[tid][0] = make_float4(q00.x, q00.y, q01.x, q01.y);
        g_gates[tid][1] = make_float4(q10.x, q10.y, q11.x, q11.y);
    }

    const int b0 = (blockIdx.x * 4 + warp) * 2;
    const int b1 = b0 + 1;
    if (b0 >= B) return;
    const bool v1 = (b1 < B);

    float acc[2][NQ];
    #pragma unroll
    for (int e = 0; e < 2; e++)
        #pragma unroll
        for (int q = 0; q < NQ; q++) acc[e][q] = 0.f;

    const float4* xr0 = (const float4*)(x + (size_t)b0 * FDIM);
    const float4* xr1 = (const float4*)(x + (size_t)(v1 ? b1 : b0) * FDIM);
    #pragma unroll
    for (int ch = 0; ch < 4; ch++) {
        float4 xv0 = xr0[ch * 32 + lane];
        float4 xv1 = xr1[ch * 32 + lane];
        #pragma unroll
        for (int q = 0; q < NQ; q++) {
            float4 wv = __ldg((const float4*)&proj_w[q * FDIM + ch * 128 + lane * 4]);
            acc[0][q] += xv0.x*wv.x + xv0.y*wv.y + xv0.z*wv.z + xv0.w*wv.w;
            acc[1][q] += xv1.x*wv.x + xv1.y*wv.y + xv1.z*wv.z + xv1.w*wv.w;
        }
    }
    auto mrgP = [&](u64 a, u64 b, int dist) -> u64 {
        u64 c = (lane & dist) ? b : a;
        u64 d = (lane & dist) ? a : b;
        return add2_(c, __shfl_xor_sync(FULL_MASK, d, dist));
    };
    u64 ap[8];
    #pragma unroll
    for (int q = 0; q < NQ; q++) ap[q] = pk2(acc[0][q], acc[1][q]);
    u64 m0 = mrgP(ap[0], ap[1], 16), m1 = mrgP(ap[2], ap[3], 16);
    u64 m2 = mrgP(ap[4], ap[5], 16), m3 = mrgP(ap[6], ap[7], 16);
    u64 n0 = mrgP(m0, m1, 8), n1 = mrgP(m2, m3, 8);
    u64 F  = mrgP(n0, n1, 4);
    F = add2_(F, __shfl_xor_sync(FULL_MASK, F, 2));
    F = add2_(F, __shfl_xor_sync(FULL_MASK, F, 1));

    if ((lane & 3) == 0) {
        const int q = ((lane >> 4) & 1) | (((lane >> 3) & 1) << 1) | (((lane >> 2) & 1) << 2);
        float dA, dB; up2(F, dA, dB);
        float hA = tanhf(dA) * 0.78539816339744830962f;
        float hB = tanhf(dB) * 0.78539816339744830962f;
        float cA, sA, cB, sB;
        __sincosf(hA, &sA, &cA);
        __sincosf(hB, &sB, &cB);
        g_cs[b0 * NQ + q] = make_float2(cA, sA);
        if (v1) g_cs[b1 * NQ + q] = make_float2(cB, sB);
    }
}

// ============================================================
// Kernel 2: circuit — 1 elem/warp, amplitudes packed by r (f32x2)
// pack j holds r = 2j (lo), 2j+1 (hi).
// Generic: new[r] = o_{pb(r)}*a[r] + p_{pb(r)}*a[r^pr in lane^pl]
// partner pack of j = maybe-swap(maybe-shfl(pack[j ^ (pr>>1)])), swap iff pr odd.
// pb(r) = parity(r & wr) via table 0x96 (compile-time per half).
// ============================================================
template<int PM, int W>
__device__ __forceinline__ void gateR(u64 R[4], u64 I[4], float4 A, float4 Bv, int lane)
{
    constexpr int pr = PM & 7, pl = PM >> 3, wr = W & 7, wl = W >> 3;
    bool bL = (wl != 0) && ((__popc(lane & wl) & 1) != 0);
    // scalar coefficients for pb=0 (A-side) / pb=1 (B-side)
    float oAx = bL ? Bv.z : A.x,  oAy = bL ? Bv.w : A.y;
    float pAx = bL ? Bv.x : A.z,  pAy = bL ? Bv.y : A.w;
    float oBx = bL ? A.x : Bv.z,  oBy = bL ? A.y : Bv.w;
    float pBx = bL ? A.z : Bv.x,  pBy = bL ? A.w : Bv.y;

    // update pack j using partner packs (Sr, Si); pb pattern compile-time
    auto upd = [&](int j, u64 Sr, u64 Si) {
        const bool pbL = (0x96 >> ((2*j)     & wr)) & 1;
        const bool pbH = (0x96 >> ((2*j + 1) & wr)) & 1;
        u64 Ox = pk2(pbL ? oBx : oAx, pbH ? oBx : oAx);
        u64 Oy = pk2(pbL ? oBy : oAy, pbH ? oBy : oAy);
        u64 Px = pk2(pbL ? pBx : pAx, pbH ? pBx : pAx);
        u64 Py = pk2(pbL ? pBy : pAy, pbH ? pBy : pAy);
        u64 nr = fma2_(neg2_(Py), Si, fma2_(Px, Sr, fma2_(neg2_(Oy), I[j], mul2_(Ox, R[j]))));
        u64 ni = fma2_(Py, Sr, fma2_(Px, Si, fma2_(Oy, R[j], mul2_(Ox, I[j]))));
        R[j] = nr; I[j] = ni;
    };

    if constexpr (pl == 0) {
        // register pairing only
        #pragma unroll
        for (int j = 0; j < 4; j++) {
            const int pj = j ^ (pr >> 1);
            if constexpr ((pr & 1) != 0) {
                if (j <= pj) {
                    if (j == pj) {   // pr==1: partner within pack
                        upd(j, swp2(R[j]), swp2(I[j]));
                    } else {
                        u64 aR = swp2(R[pj]), aI = swp2(I[pj]);
                        u64 bR = swp2(R[j]),  bI = swp2(I[j]);
                        upd(j,  aR, aI);
                        upd(pj, bR, bI);
                    }
                }
            } else {
                if (j < pj) {
                    u64 aR = R[pj], aI = I[pj];
                    u64 bR = R[j],  bI = I[j];
                    upd(j,  aR, aI);
                    upd(pj, bR, bI);
                }
            }
        }
    } else if constexpr (pr == 0) {
        // lane pairing only: partner = same pack in lane^pl
        #pragma unroll
        for (int j = 0; j < 4; j++) {
            u64 Sr = __shfl_xor_sync(FULL_MASK, R[j], pl);
            u64 Si = __shfl_xor_sync(FULL_MASK, I[j], pl);
            upd(j, Sr, Si);
        }
    } else {
        // mixed: partner = maybe-swap(shfl(pack pj))
        #pragma unroll
        for (int j = 0; j < 4; j++) {
            const int pj = j ^ (pr >> 1);
            if constexpr ((pr & 1) != 0) {
                if (j <= pj) {
                    if (j == pj) {
                        u64 Sr = swp2(__shfl_xor_sync(FULL_MASK, R[j], pl));
                        u64 Si = swp2(__shfl_xor_sync(FULL_MASK, I[j], pl));
                        upd(j, Sr, Si);
                    } else {
                        u64 aR = swp2(__shfl_xor_sync(FULL_MASK, R[pj], pl));
                        u64 aI = swp2(__shfl_xor_sync(FULL_MASK, I[pj], pl));
                        u64 bR = swp2(__shfl_xor_sync(FULL_MASK, R[j],  pl));
                        u64 bI = swp2(__shfl_xor_sync(FULL_MASK, I[j],  pl));
                        upd(j,  aR, aI);
                        upd(pj, bR, bI);
                    }
                }
            } else {
                if (j < pj) {
                    u64 aR = __shfl_xor_sync(FULL_MASK, R[pj], pl);
                    u64 aI = __shfl_xor_sync(FULL_MASK, I[pj], pl);
                    u64 bR = __shfl_xor_sync(FULL_MASK, R[j],  pl);
                    u64 bI = __shfl_xor_sync(FULL_MASK, I[j],  pl);
                    upd(j,  aR, aI);
                    upd(pj, bR, bI);
                }
            }
        }
    }
}

__global__ void __launch_bounds__(BTHREADS, 10) circuit_kernel(
    const float* __restrict__ out_w,
    const float* __restrict__ out_b,
    float* __restrict__ out,
    int B)
{
    __shared__ float4 s_g4[DEPTH * NQ][2];
    __shared__ float  s_ow[NCLS * NQ];
    __shared__ float  s_ob[NCLS];

    const int tid  = threadIdx.x;
    const int lane = tid & 31;
    const int warp = tid >> 5;

    if (tid < DEPTH * NQ * 2) ((float4*)s_g4)[tid] = ((const float4*)g_gates)[tid];
    if (tid < NCLS * NQ) s_ow[tid] = out_w[tid];
    if (tid < NCLS)      s_ob[tid] = out_b[tid];
    __syncthreads();

    auto mrg = [&](float a, float b, int dist) {
        float c = (lane & dist) ? b : a;
        float d = (lane & dist) ? a : b;
        return c + __shfl_xor_sync(FULL_MASK, d, dist);
    };
    auto srcLane = [](int q) { return ((q & 1) << 4) | (((q >> 1) & 1) << 3) | (((q >> 2) & 1) << 2); };

    const int b = blockIdx.x * 4 + warp;
    if (b >= B) return;

    float2 t = __ldg(&g_cs[b * NQ + (lane & 7)]);

    // ---- product state, lane qubits scalar ----
    float Lr = 1.f, Li = 0.f;
    #pragma unroll
    for (int k = 0; k < 5; k++) {
        const int q = k + 3;
        float c = __shfl_sync(FULL_MASK, t.x, q);
        float s = __shfl_sync(FULL_MASK, t.y, q);
        float4 V = s_g4[q][(lane >> k) & 1];
        float wx = V.x * c + V.z * s;
        float wy = V.y * c + V.w * s;
        float nr = Lr * wx - Li * wy;
        float ni = Lr * wy + Li * wx;
        Lr = nr; Li = ni;
    }
    // ---- register qubits packed: R[j] = (r=2j, 2j+1) ----
    u64 R[4], I[4];
    {
        float c = __shfl_sync(FULL_MASK, t.x, 0);
        float s = __shfl_sync(FULL_MASK, t.y, 0);
        float4 A0 = s_g4[0][0], B0 = s_g4[0][1];
        // pack X=(a0x,b0x), Y=(a0y,b0y); R[0] = (Lr+iLi)*(X+iY)
        u64 X = pk2(A0.x*c + A0.z*s, B0.x*c + B0.z*s);
        u64 Y = pk2(A0.y*c + A0.w*s, B0.y*c + B0.w*s);
        u64 lr = bc2(Lr), li = bc2(Li);
        R[0] = fma2_(neg2_(li), Y, mul2_(lr, X));
        I[0] = fma2_(li, X, mul2_(lr, Y));
    }
    {
        float c = __shfl_sync(FULL_MASK, t.x, 1);
        float s = __shfl_sync(FULL_MASK, t.y, 1);
        float4 A1 = s_g4[1][0], B1 = s_g4[1][1];
        u64 ax = bc2(A1.x*c + A1.z*s), ay = bc2(A1.y*c + A1.w*s);
        u64 bx = bc2(B1.x*c + B1.z*s), by = bc2(B1.y*c + B1.w*s);
        u64 r0 = R[0], i0 = I[0];
        R[1] = fma2_(neg2_(by), i0, mul2_(bx, r0));  I[1] = fma2_(by, r0, mul2_(bx, i0));
        R[0] = fma2_(neg2_(ay), i0, mul2_(ax, r0));  I[0] = fma2_(ay, r0, mul2_(ax, i0));
    }
    {
        float c = __shfl_sync(FULL_MASK, t.x, 2);
        float s = __shfl_sync(FULL_MASK, t.y, 2);
        float4 A2 = s_g4[2][0], B2 = s_g4[2][1];
        u64 ax = bc2(A2.x*c + A2.z*s), ay = bc2(A2.y*c + A2.w*s);
        u64 bx = bc2(B2.x*c + B2.z*s), by = bc2(B2.y*c + B2.w*s);
        #pragma unroll
        for (int j = 0; j < 2; j++) {
            u64 r0 = R[j], i0 = I[j];
            R[j + 2] = fma2_(neg2_(by), i0, mul2_(bx, r0));  I[j + 2] = fma2_(by, r0, mul2_(bx, i0));
            R[j]     = fma2_(neg2_(ay), i0, mul2_(ax, r0));  I[j]     = fma2_(ay, r0, mul2_(ax, i0));
        }
    }

    // ---- layers 1,2 with deferred-CNOT masks ----
    #define GATE(idx, PMv, Wv) gateR<PMv, Wv>(R, I, s_g4[idx][0], s_g4[idx][1], lane)
    // layer 1 (phi = C)
    GATE(8,  0x03, 0xFE); GATE(9,  0x06, 0x03); GATE(10, 0x0C, 0x07); GATE(11, 0x18, 0x0F);
    GATE(12, 0x30, 0x1F); GATE(13, 0x60, 0x3F); GATE(14, 0xC0, 0x7F); GATE(15, 0x83, 0xFF);
    // layer 2 (phi = C^2)
    GATE(16, 0x05, 0xAB); GATE(17, 0x0A, 0xFD); GATE(18, 0x14, 0xFA); GATE(19, 0x28, 0xF5);
    GATE(20, 0x50, 0xEA); GATE(21, 0xA0, 0xD5); GATE(22, 0x43, 0xAA); GATE(23, 0x86, 0x55);
    #undef GATE

    // ---- |amp|^2 packed, then scalar WHT + Z (proven tail) ----
    float S[8];
    #pragma unroll
    for (int j = 0; j < 4; j++) {
        u64 P = fma2_(I[j], I[j], mul2_(R[j], R[j]));
        up2(P, S[2*j], S[2*j + 1]);
    }
    #pragma unroll
    for (int st = 0; st < 3; st++) {
        const int d = 1 << st;
        #pragma unroll
        for (int r = 0; r < 8; r++) {
            if (!(r & d)) {
                float a = S[r] + S[r + d];
                float bm = S[r] - S[r + d];
                S[r] = a; S[r + d] = bm;
            }
        }
    }
    auto sg = [&](int wl, float v) { return (__popc(lane & wl) & 1) ? -v : v; };
    float z0 = sg(0x06, S[2]), z1 = sg(0x0A, S[6]);
    float z2 = sg(0x15, S[4]), z3 = sg(0x0B, S[1]);
    float z4 = sg(0x16, S[3]), z5 = sg(0x0C, S[6]);
    float z6 = sg(0x19, S[4]), z7 = sg(0x13, S[1]);
    float m0 = mrg(z0, z1, 16), m1 = mrg(z2, z3, 16);
    float m2 = mrg(z4, z5, 16), m3 = mrg(z6, z7, 16);
    float n0 = mrg(m0, m1, 8),  n1 = mrg(m2, m3, 8);
    float f  = mrg(n0, n1, 4);
    f += __shfl_xor_sync(FULL_MASK, f, 2);
    f += __shfl_xor_sync(FULL_MASK, f, 1);
    float g[NQ];
    #pragma unroll
    for (int q = 0; q < NQ; q++) g[q] = __shfl_sync(FULL_MASK, f, srcLane(q));

    if (lane < NCLS) {
        float o = s_ob[lane];
        #pragma unroll
        for (int q = 0; q < NQ; q++) o += g[q] * s_ow[lane * NQ + q];
        out[(size_t)b * NCLS + lane] = o;
    }
}

extern "C" void kernel_launch(void* const* d_in, const int* in_sizes, int n_in,
                              void* d_out, int out_size) {
    const float* x      = (const float*)d_in[0];
    const float* proj_w = (const float*)d_in[1];
    const float* qnn_w  = (const float*)d_in[2];
    const float* out_w  = (const float*)d_in[3];
    const float* out_b  = (const float*)d_in[4];
    float* out = (float*)d_out;

    int B = in_sizes[0] / FDIM;              // 8192
    int pblocks = (B + 7) / 8;               // 1024: proj, 2 elems/warp
    int cblocks = (B + 3) / 4;               // 2048: circuit, 1 elem/warp
    proj_kernel<<<pblocks, BTHREADS>>>(x, proj_w, qnn_w, B);
    circuit_kernel<<<cblocks, BTHREADS>>>(out_w, out_b, out, B);
}